// round 13
// baseline (speedup 1.0000x reference)
#include <cuda_runtime.h>
#include <cuda_fp16.h>
#include <stdint.h>

#define N_ROWS 32768
#define KCODES 1024
#define DDIM   256

#define Q_ELEMS 8388608LL      // 32*256*32*32
#define E_ELEMS 33554432LL     // 32768*1024
#define I_ELEMS 32768LL

__device__ float g_ee[KCODES];
__device__ float g_xx[N_ROWS];
__device__ int   g_idx[N_ROWS];
__device__ float g_partial[512];
__device__ __align__(16) __half g_X1[N_ROWS * DDIM];
__device__ __align__(16) __half g_E1[KCODES * DDIM];
__device__ __align__(16) float g_XT[N_ROWS * DDIM];   // exact fp32 transposed x

// ======================= baseline-PTX helpers ==============================
__device__ __forceinline__ uint32_t smem_u32(const void* p) {
    uint32_t a;
    asm("{ .reg .u64 t; cvta.to.shared.u64 t, %1; cvt.u32.u64 %0, t; }" : "=r"(a) : "l"(p));
    return a;
}
#define CP16(dst, src) \
    asm volatile("cp.async.cg.shared.global [%0], [%1], 16;" :: "r"(dst), "l"(src))
#define CP_COMMIT() asm volatile("cp.async.commit_group;" ::: "memory")

#define LDSM4(r, a) \
    asm volatile("ldmatrix.sync.aligned.m8n8.x4.shared.b16 {%0,%1,%2,%3}, [%4];" \
        : "=r"((r)[0]), "=r"((r)[1]), "=r"((r)[2]), "=r"((r)[3]) : "r"(a))

#define MMA16816(d, a, b0v, b1v) \
    asm volatile("mma.sync.aligned.m16n8k16.row.col.f32.f16.f16.f32 " \
        "{%0,%1,%2,%3}, {%4,%5,%6,%7}, {%8,%9}, {%0,%1,%2,%3};" \
        : "+f"((d)[0]), "+f"((d)[1]), "+f"((d)[2]), "+f"((d)[3]) \
        : "r"((a)[0]), "r"((a)[1]), "r"((a)[2]), "r"((a)[3]), "r"(b0v), "r"(b1v))

// ======================= precompute: ee + E1 ===============================
__global__ void k_prep_cb(const float* __restrict__ cb) {
    int code = blockIdx.x * 8 + (threadIdx.x >> 5);
    int lane = threadIdx.x & 31;
    const float* row = cb + code * DDIM;
    double s = 0.0;
#pragma unroll
    for (int i = 0; i < 8; i++) {
        float v = row[lane + i * 32];
        s += (double)v * v;
        g_E1[code * DDIM + lane + i * 32] = __float2half(v);
    }
#pragma unroll
    for (int m = 16; m; m >>= 1) s += __shfl_xor_sync(0xffffffffu, s, m);
    if (lane == 0) g_ee[code] = (float)s;
}

// ====== transpose + fp32 XT + fp16 X1 + xx, fused. grid 1024, block 256 ====
__global__ void k_splitxx(const float* __restrict__ x) {
    __shared__ float s[256][33];
    int bid = blockIdx.x;
    int b = bid >> 5, hw0 = (bid & 31) * 32;
    int tx = threadIdx.x & 31, ty = threadIdx.x >> 5;
    const float* xb = x + (size_t)b * 262144 + hw0 + tx;
#pragma unroll 8
    for (int g = 0; g < 32; g++) {
        int c = ty + g * 8;
        s[c][tx] = xb[(size_t)c * 1024];
    }
    __syncthreads();
    int wid = ty, lane = tx;
#pragma unroll
    for (int rr = 0; rr < 4; rr++) {
        int r = wid * 4 + rr;
        int n = b * 1024 + hw0 + r;
        double acc = 0.0;
#pragma unroll
        for (int j = 0; j < 8; j++) {
            int d = lane + j * 32;
            float v = s[d][r];
            acc += (double)v * v;
            g_XT[(size_t)n * 256 + d] = v;
            g_X1[(size_t)n * 256 + d] = __float2half(v);
        }
#pragma unroll
        for (int m = 16; m; m >>= 1) acc += __shfl_xor_sync(0xffffffffu, acc, m);
        if (lane == 0) g_xx[n] = (float)acc;
    }
}

// ======================= HMMA distance GEMM + in-CTA argmin ================
// (round-10 structure verbatim; dtype fp16)
#define A_ROWS  64
#define A_PITCH 528
#define SM_B    33792                      // 64*528
#define B_PITCH 144
#define BSTG    18432
#define SM_ES   (SM_B + 3 * BSTG)          // 89088
#define SM_XS   (SM_ES + 4096)             // 93184
#define SM_RMIN (SM_XS + 256)              // 93440
#define SM_CCNT (SM_RMIN + 256)            // 93696
#define SM_CAND (SM_CCNT + 256)            // 93952
#define MAXCAND 32
#define DIST_SMEM (SM_CAND + A_ROWS * MAXCAND * 4)   // 102144
#define TAU 1e-3f

__device__ __forceinline__ void issue_b(uint32_t smem0, int stg, int t, int tid) {
    int nb = t >> 2, kc = t & 3;
    uint32_t dstb = smem0 + SM_B + stg * BSTG;
#pragma unroll
    for (int i = 0; i < 4; i++) {
        int idx = tid + i * 256;
        int r = idx >> 3, g = idx & 7;
        CP16(dstb + r * B_PITCH + g * 16,
             g_E1 + (size_t)(nb * 128 + r) * 256 + kc * 64 + g * 8);
    }
    CP_COMMIT();
}

__global__ void __launch_bounds__(256, 2) k_dist_mma(const float* __restrict__ cb) {
    extern __shared__ char smem[];
    float* es = (float*)(smem + SM_ES);
    float* xs = (float*)(smem + SM_XS);
    int* rowmin = (int*)(smem + SM_RMIN);
    int* ccnt = (int*)(smem + SM_CCNT);
    int* cand = (int*)(smem + SM_CAND);

    int tid = threadIdx.x, lane = tid & 31, wid = tid >> 5;
    int warp_m = wid & 1, warp_n = wid >> 1;
    int n0 = blockIdx.x * A_ROWS;
    uint32_t smem0 = smem_u32(smem);

    // A resident: 64 rows x 512B
#pragma unroll
    for (int i = 0; i < 8; i++) {
        int idx = tid + i * 256;
        int r = idx >> 5, g = idx & 31;
        CP16(smem0 + r * A_PITCH + g * 16, g_X1 + (size_t)(n0 + r) * 256 + g * 8);
    }
    CP_COMMIT();
    issue_b(smem0, 0, 0, tid);
    issue_b(smem0, 1, 1, tid);

    for (int i = tid; i < KCODES; i += 256) es[i] = g_ee[i];
    if (tid < A_ROWS) {
        xs[tid] = g_xx[n0 + tid];
        rowmin[tid] = 0x7F800000;   // +inf
        ccnt[tid] = 0;
    }

    uint32_t a_base = smem0 + (warp_m * 32 + (lane & 15)) * A_PITCH + (lane >> 4) * 16;
    uint32_t b_base = smem0 + SM_B + (warp_n * 32 + (lane & 7)) * B_PITCH + (lane >> 3) * 16;

    int gq = lane >> 2, iq = lane & 3;

    for (int nb = 0; nb < 8; nb++) {
        float acc[2][4][4];
#pragma unroll
        for (int mt = 0; mt < 2; mt++)
#pragma unroll
            for (int nt = 0; nt < 4; nt++)
#pragma unroll
                for (int q = 0; q < 4; q++) acc[mt][nt][q] = 0.0f;

        for (int kc = 0; kc < 4; kc++) {
            int t = nb * 4 + kc;
            if (t + 2 < 32) issue_b(smem0, (t + 2) % 3, t + 2, tid);
            if (t < 30)       asm volatile("cp.async.wait_group 2;" ::: "memory");
            else if (t == 30) asm volatile("cp.async.wait_group 1;" ::: "memory");
            else              asm volatile("cp.async.wait_group 0;" ::: "memory");
            __syncthreads();

            uint32_t bst = b_base + (t % 3) * BSTG;
            uint32_t ab = a_base + kc * 128;
#pragma unroll
            for (int kh = 0; kh < 2; kh++) {
                uint32_t bfr[4][4];
#pragma unroll
                for (int nt = 0; nt < 4; nt++)
                    LDSM4(bfr[nt], bst + nt * (8 * B_PITCH) + kh * 64);
#pragma unroll
                for (int ks = 0; ks < 2; ks++) {
                    uint32_t afr[2][4];
#pragma unroll
                    for (int mt = 0; mt < 2; mt++)
                        LDSM4(afr[mt], ab + mt * (16 * A_PITCH) + kh * 64 + ks * 32);
#pragma unroll
                    for (int mt = 0; mt < 2; mt++)
#pragma unroll
                        for (int nt = 0; nt < 4; nt++)
                            MMA16816(acc[mt][nt], afr[mt], bfr[nt][ks * 2], bfr[nt][ks * 2 + 1]);
                }
            }
            __syncthreads();
        }

        // ---- epilogue phase 1: per-row running min ----
#pragma unroll
        for (int mt = 0; mt < 2; mt++) {
#pragma unroll
            for (int h = 0; h < 2; h++) {
                int mrow = warp_m * 32 + mt * 16 + gq + h * 8;
                float xv = xs[mrow];
                float dmin = 3.4e38f;
#pragma unroll
                for (int nt = 0; nt < 4; nt++) {
                    int nbase = nb * 128 + warp_n * 32 + nt * 8 + 2 * iq;
                    float d0 = (xv + es[nbase])     - 2.0f * acc[mt][nt][h * 2 + 0];
                    float d1 = (xv + es[nbase + 1]) - 2.0f * acc[mt][nt][h * 2 + 1];
                    dmin = fminf(dmin, fminf(d0, d1));
                }
                atomicMin(&rowmin[mrow], __float_as_int(dmin));
            }
        }
        __syncthreads();
        // ---- epilogue phase 2: tight capture ----
#pragma unroll
        for (int mt = 0; mt < 2; mt++) {
#pragma unroll
            for (int h = 0; h < 2; h++) {
                int mrow = warp_m * 32 + mt * 16 + gq + h * 8;
                float xv = xs[mrow];
                float thr = __int_as_float(rowmin[mrow]) + TAU;
#pragma unroll
                for (int nt = 0; nt < 4; nt++) {
                    int nbase = nb * 128 + warp_n * 32 + nt * 8 + 2 * iq;
                    float d0 = (xv + es[nbase])     - 2.0f * acc[mt][nt][h * 2 + 0];
                    float d1 = (xv + es[nbase + 1]) - 2.0f * acc[mt][nt][h * 2 + 1];
                    if (d0 <= thr) {
                        int slot = atomicAdd(&ccnt[mrow], 1);
                        if (slot < MAXCAND) cand[mrow * MAXCAND + slot] = nbase;
                    }
                    if (d1 <= thr) {
                        int slot = atomicAdd(&ccnt[mrow], 1);
                        if (slot < MAXCAND) cand[mrow * MAXCAND + slot] = nbase + 1;
                    }
                }
            }
        }
    }
    __syncthreads();

    // exact fp32 rescore: warp w handles rows w*8..w*8+7
    for (int rr = 0; rr < 8; rr++) {
        int rl = wid * 8 + rr;
        int row = n0 + rl;
        int cnt = ccnt[rl];
        float xx = g_xx[row];
        const float4* xr4 = (const float4*)(g_XT + (size_t)row * 256 + lane * 8);
        float4 xa = xr4[0], xb4 = xr4[1];
        float best = 3.4e38f; int bidx = 0x7fffffff;
        bool overflow = (cnt > MAXCAND);
        int total = overflow ? KCODES : cnt;
        for (int c = 0; c < total; c++) {
            int k = overflow ? c : cand[rl * MAXCAND + c];
            const float4* cr = (const float4*)(cb + (size_t)k * 256 + lane * 8);
            float4 ca = cr[0], cbv = cr[1];
            float p = xa.x * ca.x;
            p = fmaf(xa.y, ca.y, p);
            p = fmaf(xa.z, ca.z, p);
            p = fmaf(xa.w, ca.w, p);
            p = fmaf(xb4.x, cbv.x, p);
            p = fmaf(xb4.y, cbv.y, p);
            p = fmaf(xb4.z, cbv.z, p);
            p = fmaf(xb4.w, cbv.w, p);
#pragma unroll
            for (int m = 16; m; m >>= 1) p += __shfl_xor_sync(0xffffffffu, p, m);
            float dd = (xx + es[k]) - 2.0f * p;
            if (dd < best || (dd == best && k < bidx)) { best = dd; bidx = k; }
        }
        if (lane == 0) g_idx[row] = bidx;
    }
}

// ============ merged outputs: quantized + SSE + one-hot + indices ==========
// one CTA per 64 rows; dynamic smem: qs[64*257]f | ids[64]i | red[256]f
#define OS_QS   0
#define OS_IDS  65792
#define OS_RED  66048
#define OUT_SMEM 67072
#define QS_PITCH 257

__global__ void __launch_bounds__(256) k_outputs(
        const float* __restrict__ x, const float* __restrict__ cb,
        float* __restrict__ outq, float* __restrict__ enc,
        float* __restrict__ outi, int en_q, int en_e, int en_i) {
    extern __shared__ char osm[];
    float* qs = (float*)(osm + OS_QS);
    int* ids = (int*)(osm + OS_IDS);
    float* red = (float*)(osm + OS_RED);

    int tid = threadIdx.x;
    int n0 = blockIdx.x * 64;
    if (tid < 64) ids[tid] = g_idx[n0 + tid];
    __syncthreads();

    // stage selected codebook rows (coalesced)
    for (int j = 0; j < 64; j++)
        qs[j * QS_PITCH + tid] = cb[(size_t)ids[j] * 256 + tid];
    __syncthreads();

    // quantized straight-through + SSE
    int b = n0 >> 10, hwbase = n0 & 1023;
    int hwl = tid & 63, cpart = tid >> 6;
    float sse = 0.0f;
    {
        size_t xoff = ((size_t)b * 256 + cpart) * 1024 + hwbase + hwl;
        const float* qrow = qs + hwl * QS_PITCH + cpart;
        for (int c = cpart; c < 256; c += 4) {
            float in = x[xoff];
            float q = qrow[c - cpart];
            float diff = q - in;
            if (en_q) outq[xoff] = in + diff;
            sse = fmaf(diff, diff, sse);
            xoff += 4096;
        }
    }

    // one-hot rows (scalar stores; enc slab only 4B-aligned)
    if (en_e) {
        for (int j = 0; j < 64; j++) {
            int idx = ids[j];
            float* dst = enc + (size_t)(n0 + j) * 1024;
#pragma unroll
            for (int rep = 0; rep < 4; rep++) {
                int col = tid + rep * 256;
                dst[col] = (col == idx) ? 1.0f : 0.0f;
            }
        }
    }
    if (en_i && tid < 64) outi[n0 + tid] = (float)ids[tid];

    red[tid] = sse;
    __syncthreads();
    for (int s = 128; s; s >>= 1) {
        if (tid < s) red[tid] += red[tid + s];
        __syncthreads();
    }
    if (tid == 0) g_partial[blockIdx.x] = red[0];
}

// ======================= loss finalize =====================================
__global__ void k_loss(float* __restrict__ out_loss) {
    __shared__ float red[256];
    float s = g_partial[threadIdx.x * 2] + g_partial[threadIdx.x * 2 + 1];
    red[threadIdx.x] = s;
    __syncthreads();
    for (int t = 128; t; t >>= 1) {
        if (threadIdx.x < t) red[threadIdx.x] += red[threadIdx.x + t];
        __syncthreads();
    }
    if (threadIdx.x == 0) {
        float m = red[0] / 8388608.0f;
        out_loss[0] = m + 0.25f * m;
    }
}

// ===========================================================================
extern "C" void kernel_launch(void* const* d_in, const int* in_sizes, int n_in,
                              void* d_out, int out_size) {
    const float* x  = (const float*)d_in[0];
    const float* cb = (const float*)d_in[1];
    if (n_in >= 2 && in_sizes[0] == KCODES * DDIM && in_sizes[1] == (int)Q_ELEMS) {
        const float* t = x; x = cb; cb = t;
    }
    float* out = (float*)d_out;

    long long os = (long long)out_size;
    long long off_loss = -1, off_q = -1, off_e = -1, off_i = -1;
    if (os == 1 + Q_ELEMS + E_ELEMS + I_ELEMS) {
        off_loss = 0; off_q = 1; off_e = 1 + Q_ELEMS; off_i = 1 + Q_ELEMS + E_ELEMS;
    } else if (os == Q_ELEMS) {
        off_q = 0;
    } else if (os == 1) {
        off_loss = 0;
    } else if (os == 1 + Q_ELEMS) {
        off_loss = 0; off_q = 1;
    } else {
        if (os >= 1) off_loss = 0;
        if (os >= 1 + Q_ELEMS) off_q = 1;
        if (os >= 1 + Q_ELEMS + E_ELEMS) off_e = 1 + Q_ELEMS;
        if (os >= 1 + Q_ELEMS + E_ELEMS + I_ELEMS) off_i = 1 + Q_ELEMS + E_ELEMS;
    }

    cudaFuncSetAttribute(k_dist_mma, cudaFuncAttributeMaxDynamicSharedMemorySize, DIST_SMEM);
    cudaFuncSetAttribute(k_outputs, cudaFuncAttributeMaxDynamicSharedMemorySize, OUT_SMEM);

    k_prep_cb<<<128, 256>>>(cb);
    k_splitxx<<<1024, 256>>>(x);
    k_dist_mma<<<512, 256, DIST_SMEM>>>(cb);

    k_outputs<<<512, 256, OUT_SMEM>>>(
        x, cb,
        (off_q >= 0) ? (out + off_q) : out,
        (off_e >= 0) ? (out + off_e) : out,
        (off_i >= 0) ? (out + off_i) : out,
        (off_q >= 0) ? 1 : 0, (off_e >= 0) ? 1 : 0, (off_i >= 0) ? 1 : 0);

    if (off_loss >= 0) k_loss<<<1, 256>>>(out + off_loss);
}

// round 14
// speedup vs baseline: 1.2665x; 1.2665x over previous
#include <cuda_runtime.h>
#include <cuda_bf16.h>
#include <stdint.h>

#define N_ROWS 32768
#define KCODES 1024
#define DDIM   256

#define Q_ELEMS 8388608LL      // 32*256*32*32
#define E_ELEMS 33554432LL     // 32768*1024
#define I_ELEMS 32768LL

__device__ float g_ee[KCODES];
__device__ float g_xx[N_ROWS];
__device__ int   g_idx[N_ROWS];
__device__ float g_partial[8192];
__device__ __align__(16) __nv_bfloat16 g_X1[N_ROWS * DDIM];
__device__ __align__(16) __nv_bfloat16 g_E1[KCODES * DDIM];
__device__ __align__(16) float g_XT[N_ROWS * DDIM];   // exact fp32 transposed x

// ======================= baseline-PTX helpers ==============================
__device__ __forceinline__ uint32_t smem_u32(const void* p) {
    uint32_t a;
    asm("{ .reg .u64 t; cvta.to.shared.u64 t, %1; cvt.u32.u64 %0, t; }" : "=r"(a) : "l"(p));
    return a;
}
#define CP16(dst, src) \
    asm volatile("cp.async.cg.shared.global [%0], [%1], 16;" :: "r"(dst), "l"(src))
#define CP_COMMIT() asm volatile("cp.async.commit_group;" ::: "memory")

#define LDSM4(r, a) \
    asm volatile("ldmatrix.sync.aligned.m8n8.x4.shared.b16 {%0,%1,%2,%3}, [%4];" \
        : "=r"((r)[0]), "=r"((r)[1]), "=r"((r)[2]), "=r"((r)[3]) : "r"(a))

#define MMA16816(d, a, b0v, b1v) \
    asm volatile("mma.sync.aligned.m16n8k16.row.col.f32.bf16.bf16.f32 " \
        "{%0,%1,%2,%3}, {%4,%5,%6,%7}, {%8,%9}, {%0,%1,%2,%3};" \
        : "+f"((d)[0]), "+f"((d)[1]), "+f"((d)[2]), "+f"((d)[3]) \
        : "r"((a)[0]), "r"((a)[1]), "r"((a)[2]), "r"((a)[3]), "r"(b0v), "r"(b1v))

// ======================= precompute: ee + E1 ===============================
__global__ void k_prep_cb(const float* __restrict__ cb) {
    int code = blockIdx.x * 8 + (threadIdx.x >> 5);
    int lane = threadIdx.x & 31;
    const float* row = cb + code * DDIM;
    double s = 0.0;
#pragma unroll
    for (int i = 0; i < 8; i++) {
        float v = row[lane + i * 32];
        s += (double)v * v;
        g_E1[code * DDIM + lane + i * 32] = __float2bfloat16(v);
    }
#pragma unroll
    for (int m = 16; m; m >>= 1) s += __shfl_xor_sync(0xffffffffu, s, m);
    if (lane == 0) g_ee[code] = (float)s;
}

// ====== transpose + fp32 XT + bf16 X1 + xx, fused. grid 1024, block 256 ====
__global__ void k_splitxx(const float* __restrict__ x) {
    __shared__ float s[256][33];
    int bid = blockIdx.x;
    int b = bid >> 5, hw0 = (bid & 31) * 32;
    int tx = threadIdx.x & 31, ty = threadIdx.x >> 5;
    const float* xb = x + (size_t)b * 262144 + hw0 + tx;
#pragma unroll 8
    for (int g = 0; g < 32; g++) {
        int c = ty + g * 8;
        s[c][tx] = xb[(size_t)c * 1024];
    }
    __syncthreads();
    int wid = ty, lane = tx;
#pragma unroll
    for (int rr = 0; rr < 4; rr++) {
        int r = wid * 4 + rr;
        int n = b * 1024 + hw0 + r;
        double acc = 0.0;
#pragma unroll
        for (int j = 0; j < 8; j++) {
            int d = lane + j * 32;
            float v = s[d][r];
            acc += (double)v * v;
            g_XT[(size_t)n * 256 + d] = v;
            g_X1[(size_t)n * 256 + d] = __float2bfloat16(v);
        }
#pragma unroll
        for (int m = 16; m; m >>= 1) acc += __shfl_xor_sync(0xffffffffu, acc, m);
        if (lane == 0) g_xx[n] = (float)acc;
    }
}

// ======================= HMMA distance GEMM + in-CTA argmin ================
// (round-10 proven configuration, bf16)
#define A_ROWS  64
#define A_PITCH 528
#define SM_B    33792                      // 64*528
#define B_PITCH 144
#define BSTG    18432
#define SM_ES   (SM_B + 3 * BSTG)          // 89088
#define SM_XS   (SM_ES + 4096)             // 93184
#define SM_RMIN (SM_XS + 256)              // 93440
#define SM_CCNT (SM_RMIN + 256)            // 93696
#define SM_CAND (SM_CCNT + 256)            // 93952
#define MAXCAND 32
#define DIST_SMEM (SM_CAND + A_ROWS * MAXCAND * 4)   // 102144
#define TAU 1e-3f

__device__ __forceinline__ void issue_b(uint32_t smem0, int stg, int t, int tid) {
    int nb = t >> 2, kc = t & 3;
    uint32_t dstb = smem0 + SM_B + stg * BSTG;
#pragma unroll
    for (int i = 0; i < 4; i++) {
        int idx = tid + i * 256;
        int r = idx >> 3, g = idx & 7;
        CP16(dstb + r * B_PITCH + g * 16,
             g_E1 + (size_t)(nb * 128 + r) * 256 + kc * 64 + g * 8);
    }
    CP_COMMIT();
}

__global__ void __launch_bounds__(256, 2) k_dist_mma(const float* __restrict__ cb) {
    extern __shared__ char smem[];
    float* es = (float*)(smem + SM_ES);
    float* xs = (float*)(smem + SM_XS);
    int* rowmin = (int*)(smem + SM_RMIN);
    int* ccnt = (int*)(smem + SM_CCNT);
    int* cand = (int*)(smem + SM_CAND);

    int tid = threadIdx.x, lane = tid & 31, wid = tid >> 5;
    int warp_m = wid & 1, warp_n = wid >> 1;
    int n0 = blockIdx.x * A_ROWS;
    uint32_t smem0 = smem_u32(smem);

    // A resident: 64 rows x 512B
#pragma unroll
    for (int i = 0; i < 8; i++) {
        int idx = tid + i * 256;
        int r = idx >> 5, g = idx & 31;
        CP16(smem0 + r * A_PITCH + g * 16, g_X1 + (size_t)(n0 + r) * 256 + g * 8);
    }
    CP_COMMIT();
    issue_b(smem0, 0, 0, tid);
    issue_b(smem0, 1, 1, tid);

    for (int i = tid; i < KCODES; i += 256) es[i] = g_ee[i];
    if (tid < A_ROWS) {
        xs[tid] = g_xx[n0 + tid];
        rowmin[tid] = 0x7F800000;   // +inf
        ccnt[tid] = 0;
    }

    uint32_t a_base = smem0 + (warp_m * 32 + (lane & 15)) * A_PITCH + (lane >> 4) * 16;
    uint32_t b_base = smem0 + SM_B + (warp_n * 32 + (lane & 7)) * B_PITCH + (lane >> 3) * 16;

    int gq = lane >> 2, iq = lane & 3;

    for (int nb = 0; nb < 8; nb++) {
        float acc[2][4][4];
#pragma unroll
        for (int mt = 0; mt < 2; mt++)
#pragma unroll
            for (int nt = 0; nt < 4; nt++)
#pragma unroll
                for (int q = 0; q < 4; q++) acc[mt][nt][q] = 0.0f;

        for (int kc = 0; kc < 4; kc++) {
            int t = nb * 4 + kc;
            if (t + 2 < 32) issue_b(smem0, (t + 2) % 3, t + 2, tid);
            if (t < 30)       asm volatile("cp.async.wait_group 2;" ::: "memory");
            else if (t == 30) asm volatile("cp.async.wait_group 1;" ::: "memory");
            else              asm volatile("cp.async.wait_group 0;" ::: "memory");
            __syncthreads();

            uint32_t bst = b_base + (t % 3) * BSTG;
            uint32_t ab = a_base + kc * 128;
#pragma unroll
            for (int kh = 0; kh < 2; kh++) {
                uint32_t bfr[4][4];
#pragma unroll
                for (int nt = 0; nt < 4; nt++)
                    LDSM4(bfr[nt], bst + nt * (8 * B_PITCH) + kh * 64);
#pragma unroll
                for (int ks = 0; ks < 2; ks++) {
                    uint32_t afr[2][4];
#pragma unroll
                    for (int mt = 0; mt < 2; mt++)
                        LDSM4(afr[mt], ab + mt * (16 * A_PITCH) + kh * 64 + ks * 32);
#pragma unroll
                    for (int mt = 0; mt < 2; mt++)
#pragma unroll
                        for (int nt = 0; nt < 4; nt++)
                            MMA16816(acc[mt][nt], afr[mt], bfr[nt][ks * 2], bfr[nt][ks * 2 + 1]);
                }
            }
            __syncthreads();
        }

        // ---- epilogue phase 1: per-row running min ----
#pragma unroll
        for (int mt = 0; mt < 2; mt++) {
#pragma unroll
            for (int h = 0; h < 2; h++) {
                int mrow = warp_m * 32 + mt * 16 + gq + h * 8;
                float xv = xs[mrow];
                float dmin = 3.4e38f;
#pragma unroll
                for (int nt = 0; nt < 4; nt++) {
                    int nbase = nb * 128 + warp_n * 32 + nt * 8 + 2 * iq;
                    float d0 = (xv + es[nbase])     - 2.0f * acc[mt][nt][h * 2 + 0];
                    float d1 = (xv + es[nbase + 1]) - 2.0f * acc[mt][nt][h * 2 + 1];
                    dmin = fminf(dmin, fminf(d0, d1));
                }
                atomicMin(&rowmin[mrow], __float_as_int(dmin));
            }
        }
        __syncthreads();
        // ---- epilogue phase 2: tight capture ----
#pragma unroll
        for (int mt = 0; mt < 2; mt++) {
#pragma unroll
            for (int h = 0; h < 2; h++) {
                int mrow = warp_m * 32 + mt * 16 + gq + h * 8;
                float xv = xs[mrow];
                float thr = __int_as_float(rowmin[mrow]) + TAU;
#pragma unroll
                for (int nt = 0; nt < 4; nt++) {
                    int nbase = nb * 128 + warp_n * 32 + nt * 8 + 2 * iq;
                    float d0 = (xv + es[nbase])     - 2.0f * acc[mt][nt][h * 2 + 0];
                    float d1 = (xv + es[nbase + 1]) - 2.0f * acc[mt][nt][h * 2 + 1];
                    if (d0 <= thr) {
                        int slot = atomicAdd(&ccnt[mrow], 1);
                        if (slot < MAXCAND) cand[mrow * MAXCAND + slot] = nbase;
                    }
                    if (d1 <= thr) {
                        int slot = atomicAdd(&ccnt[mrow], 1);
                        if (slot < MAXCAND) cand[mrow * MAXCAND + slot] = nbase + 1;
                    }
                }
            }
        }
    }
    __syncthreads();

    // exact fp32 rescore: warp w handles rows w*8..w*8+7
    for (int rr = 0; rr < 8; rr++) {
        int rl = wid * 8 + rr;
        int row = n0 + rl;
        int cnt = ccnt[rl];
        float xx = g_xx[row];
        const float4* xr4 = (const float4*)(g_XT + (size_t)row * 256 + lane * 8);
        float4 xa = xr4[0], xb4 = xr4[1];
        float best = 3.4e38f; int bidx = 0x7fffffff;
        bool overflow = (cnt > MAXCAND);
        int total = overflow ? KCODES : cnt;
        for (int c = 0; c < total; c++) {
            int k = overflow ? c : cand[rl * MAXCAND + c];
            const float4* cr = (const float4*)(cb + (size_t)k * 256 + lane * 8);
            float4 ca = cr[0], cbv = cr[1];
            float p = xa.x * ca.x;
            p = fmaf(xa.y, ca.y, p);
            p = fmaf(xa.z, ca.z, p);
            p = fmaf(xa.w, ca.w, p);
            p = fmaf(xb4.x, cbv.x, p);
            p = fmaf(xb4.y, cbv.y, p);
            p = fmaf(xb4.z, cbv.z, p);
            p = fmaf(xb4.w, cbv.w, p);
#pragma unroll
            for (int m = 16; m; m >>= 1) p += __shfl_xor_sync(0xffffffffu, p, m);
            float dd = (xx + es[k]) - 2.0f * p;
            if (dd < best || (dd == best && k < bidx)) { best = dd; bidx = k; }
        }
        if (lane == 0) g_idx[row] = bidx;
    }
}

// ======================= outputs (round-10 proven shapes) ==================
__global__ void k_quant2(const float* __restrict__ x, const float* __restrict__ cb,
                         float* __restrict__ outq, float* __restrict__ outi,
                         int en, int ei) {
    __shared__ float xs[32][33];
    __shared__ float qs[32][33];
    __shared__ int ids[32];
    int bid = blockIdx.x;
    int b = bid >> 8, ct = (bid >> 5) & 7, ht = bid & 31;
    int tx = threadIdx.x & 31, ty = threadIdx.x >> 5;
    if (threadIdx.x < 32) ids[threadIdx.x] = g_idx[(b << 10) + ht * 32 + threadIdx.x];
#pragma unroll
    for (int r = 0; r < 4; r++)
        xs[ty + r * 8][tx] = x[(((size_t)b * 256 + ct * 32 + ty + r * 8) << 10) + ht * 32 + tx];
    __syncthreads();
#pragma unroll
    for (int r = 0; r < 4; r++) {
        int nl = ty + r * 8;
        qs[tx][nl] = cb[(size_t)ids[nl] * 256 + ct * 32 + tx];
    }
    __syncthreads();
    float local = 0.0f;
#pragma unroll
    for (int r = 0; r < 4; r++) {
        int cl = ty + r * 8;
        float in = xs[cl][tx];
        float q = qs[cl][tx];
        float diff = q - in;
        if (en) outq[(((size_t)b * 256 + ct * 32 + cl) << 10) + ht * 32 + tx] = in + diff;
        local = fmaf(diff, diff, local);
    }
    // indices output folded in (ct==0 blocks only, one per 32 rows)
    if (ei && ct == 0 && threadIdx.x < 32)
        outi[(b << 10) + ht * 32 + threadIdx.x] = (float)ids[threadIdx.x];
    __shared__ float red[256];
    red[threadIdx.x] = local;
    __syncthreads();
    for (int sfr = 128; sfr; sfr >>= 1) {
        if (threadIdx.x < sfr) red[threadIdx.x] += red[threadIdx.x + sfr];
        __syncthreads();
    }
    if (threadIdx.x == 0) g_partial[bid] = red[0];
}

__global__ void k_loss(float* __restrict__ out_loss) {
    __shared__ float red[256];
    float s = 0.0f;
    int base = threadIdx.x * 32;
#pragma unroll
    for (int i = 0; i < 32; i++) s += g_partial[base + i];
    red[threadIdx.x] = s;
    __syncthreads();
    for (int t = 128; t; t >>= 1) {
        if (threadIdx.x < t) red[threadIdx.x] += red[threadIdx.x + t];
        __syncthreads();
    }
    if (threadIdx.x == 0) {
        float m = red[0] / 8388608.0f;
        out_loss[0] = m + 0.25f * m;
    }
}

// streaming zeros + one-hot (SCALAR stores — slab 4B-aligned only)
__global__ void k_encodings(float* __restrict__ enc) {
    int n = blockIdx.x * 8 + (threadIdx.x >> 5);
    int lane = threadIdx.x & 31;
    int idx = g_idx[n];
    float* dst = enc + (size_t)n * 1024;
#pragma unroll
    for (int i = 0; i < 32; i++) {
        int j = lane + i * 32;
        dst[j] = (j == idx) ? 1.0f : 0.0f;
    }
}

// ===========================================================================
extern "C" void kernel_launch(void* const* d_in, const int* in_sizes, int n_in,
                              void* d_out, int out_size) {
    const float* x  = (const float*)d_in[0];
    const float* cb = (const float*)d_in[1];
    if (n_in >= 2 && in_sizes[0] == KCODES * DDIM && in_sizes[1] == (int)Q_ELEMS) {
        const float* t = x; x = cb; cb = t;
    }
    float* out = (float*)d_out;

    long long os = (long long)out_size;
    long long off_loss = -1, off_q = -1, off_e = -1, off_i = -1;
    if (os == 1 + Q_ELEMS + E_ELEMS + I_ELEMS) {
        off_loss = 0; off_q = 1; off_e = 1 + Q_ELEMS; off_i = 1 + Q_ELEMS + E_ELEMS;
    } else if (os == Q_ELEMS) {
        off_q = 0;
    } else if (os == 1) {
        off_loss = 0;
    } else if (os == 1 + Q_ELEMS) {
        off_loss = 0; off_q = 1;
    } else {
        if (os >= 1) off_loss = 0;
        if (os >= 1 + Q_ELEMS) off_q = 1;
        if (os >= 1 + Q_ELEMS + E_ELEMS) off_e = 1 + Q_ELEMS;
        if (os >= 1 + Q_ELEMS + E_ELEMS + I_ELEMS) off_i = 1 + Q_ELEMS + E_ELEMS;
    }

    cudaFuncSetAttribute(k_dist_mma, cudaFuncAttributeMaxDynamicSharedMemorySize, DIST_SMEM);

    k_prep_cb<<<128, 256>>>(cb);
    k_splitxx<<<1024, 256>>>(x);
    k_dist_mma<<<512, 256, DIST_SMEM>>>(cb);

    k_quant2<<<8192, 256>>>(x, cb,
                            (off_q >= 0) ? (out + off_q) : out,
                            (off_i >= 0) ? (out + off_i) : out,
                            (off_q >= 0) ? 1 : 0,
                            (off_i >= 0) ? 1 : 0);
    if (off_loss >= 0) k_loss<<<1, 256>>>(out + off_loss);

    if (off_e >= 0)
        k_encodings<<<4096, 256>>>(out + off_e);
}

// round 15
// speedup vs baseline: 1.2789x; 1.0098x over previous
#include <cuda_runtime.h>
#include <cuda_bf16.h>
#include <stdint.h>

#define N_ROWS 32768
#define KCODES 1024
#define DDIM   256

#define Q_ELEMS 8388608LL      // 32*256*32*32
#define E_ELEMS 33554432LL     // 32768*1024
#define I_ELEMS 32768LL

__device__ float g_ee[KCODES];
__device__ float g_xx[N_ROWS];
__device__ int   g_idx[N_ROWS];
__device__ float g_partial[8192];
__device__ __align__(16) __nv_bfloat16 g_X1[N_ROWS * DDIM];
__device__ __align__(16) __nv_bfloat16 g_E1[KCODES * DDIM];
__device__ __align__(16) float g_XT[N_ROWS * DDIM];   // exact fp32 transposed x

// ======================= baseline-PTX helpers ==============================
__device__ __forceinline__ uint32_t smem_u32(const void* p) {
    uint32_t a;
    asm("{ .reg .u64 t; cvta.to.shared.u64 t, %1; cvt.u32.u64 %0, t; }" : "=r"(a) : "l"(p));
    return a;
}
#define CP16(dst, src) \
    asm volatile("cp.async.cg.shared.global [%0], [%1], 16;" :: "r"(dst), "l"(src))
#define CP_COMMIT() asm volatile("cp.async.commit_group;" ::: "memory")

#define LDSM4(r, a) \
    asm volatile("ldmatrix.sync.aligned.m8n8.x4.shared.b16 {%0,%1,%2,%3}, [%4];" \
        : "=r"((r)[0]), "=r"((r)[1]), "=r"((r)[2]), "=r"((r)[3]) : "r"(a))

#define MMA16816(d, a, b0v, b1v) \
    asm volatile("mma.sync.aligned.m16n8k16.row.col.f32.bf16.bf16.f32 " \
        "{%0,%1,%2,%3}, {%4,%5,%6,%7}, {%8,%9}, {%0,%1,%2,%3};" \
        : "+f"((d)[0]), "+f"((d)[1]), "+f"((d)[2]), "+f"((d)[3]) \
        : "r"((a)[0]), "r"((a)[1]), "r"((a)[2]), "r"((a)[3]), "r"(b0v), "r"(b1v))

// ======================= precompute: ee + E1 ===============================
__global__ void k_prep_cb(const float* __restrict__ cb) {
    int code = blockIdx.x * 8 + (threadIdx.x >> 5);
    int lane = threadIdx.x & 31;
    const float* row = cb + code * DDIM;
    double s = 0.0;
#pragma unroll
    for (int i = 0; i < 8; i++) {
        float v = row[lane + i * 32];
        s += (double)v * v;
        g_E1[code * DDIM + lane + i * 32] = __float2bfloat16(v);
    }
#pragma unroll
    for (int m = 16; m; m >>= 1) s += __shfl_xor_sync(0xffffffffu, s, m);
    if (lane == 0) g_ee[code] = (float)s;
}

// ====== transpose + fp32 XT + bf16 X1 + xx, fused. grid 1024, block 256 ====
__global__ void k_splitxx(const float* __restrict__ x) {
    __shared__ float s[256][33];
    int bid = blockIdx.x;
    int b = bid >> 5, hw0 = (bid & 31) * 32;
    int tx = threadIdx.x & 31, ty = threadIdx.x >> 5;
    const float* xb = x + (size_t)b * 262144 + hw0 + tx;
#pragma unroll 8
    for (int g = 0; g < 32; g++) {
        int c = ty + g * 8;
        s[c][tx] = xb[(size_t)c * 1024];
    }
    __syncthreads();
    int wid = ty, lane = tx;
#pragma unroll
    for (int rr = 0; rr < 4; rr++) {
        int r = wid * 4 + rr;
        int n = b * 1024 + hw0 + r;
        double acc = 0.0;
#pragma unroll
        for (int j = 0; j < 8; j++) {
            int d = lane + j * 32;
            float v = s[d][r];
            acc += (double)v * v;
            g_XT[(size_t)n * 256 + d] = v;
            g_X1[(size_t)n * 256 + d] = __float2bfloat16(v);
        }
#pragma unroll
        for (int m = 16; m; m >>= 1) acc += __shfl_xor_sync(0xffffffffu, acc, m);
        if (lane == 0) g_xx[n] = (float)acc;
    }
}

// ======================= HMMA distance GEMM + in-CTA argmin ================
// (round-10 proven configuration, bf16)
#define A_ROWS  64
#define A_PITCH 528
#define SM_B    33792                      // 64*528
#define B_PITCH 144
#define BSTG    18432
#define SM_ES   (SM_B + 3 * BSTG)          // 89088
#define SM_XS   (SM_ES + 4096)             // 93184
#define SM_RMIN (SM_XS + 256)              // 93440
#define SM_CCNT (SM_RMIN + 256)            // 93696
#define SM_CAND (SM_CCNT + 256)            // 93952
#define MAXCAND 32
#define DIST_SMEM (SM_CAND + A_ROWS * MAXCAND * 4)   // 102144
#define TAU 1e-3f

__device__ __forceinline__ void issue_b(uint32_t smem0, int stg, int t, int tid) {
    int nb = t >> 2, kc = t & 3;
    uint32_t dstb = smem0 + SM_B + stg * BSTG;
#pragma unroll
    for (int i = 0; i < 4; i++) {
        int idx = tid + i * 256;
        int r = idx >> 3, g = idx & 7;
        CP16(dstb + r * B_PITCH + g * 16,
             g_E1 + (size_t)(nb * 128 + r) * 256 + kc * 64 + g * 8);
    }
    CP_COMMIT();
}

__global__ void __launch_bounds__(256, 2) k_dist_mma(const float* __restrict__ cb) {
    extern __shared__ char smem[];
    float* es = (float*)(smem + SM_ES);
    float* xs = (float*)(smem + SM_XS);
    int* rowmin = (int*)(smem + SM_RMIN);
    int* ccnt = (int*)(smem + SM_CCNT);
    int* cand = (int*)(smem + SM_CAND);

    int tid = threadIdx.x, lane = tid & 31, wid = tid >> 5;
    int warp_m = wid & 1, warp_n = wid >> 1;
    int n0 = blockIdx.x * A_ROWS;
    uint32_t smem0 = smem_u32(smem);

    // A resident: 64 rows x 512B
#pragma unroll
    for (int i = 0; i < 8; i++) {
        int idx = tid + i * 256;
        int r = idx >> 5, g = idx & 31;
        CP16(smem0 + r * A_PITCH + g * 16, g_X1 + (size_t)(n0 + r) * 256 + g * 8);
    }
    CP_COMMIT();
    issue_b(smem0, 0, 0, tid);
    issue_b(smem0, 1, 1, tid);

    for (int i = tid; i < KCODES; i += 256) es[i] = g_ee[i];
    if (tid < A_ROWS) {
        xs[tid] = g_xx[n0 + tid];
        rowmin[tid] = 0x7F800000;   // +inf
        ccnt[tid] = 0;
    }

    uint32_t a_base = smem0 + (warp_m * 32 + (lane & 15)) * A_PITCH + (lane >> 4) * 16;
    uint32_t b_base = smem0 + SM_B + (warp_n * 32 + (lane & 7)) * B_PITCH + (lane >> 3) * 16;

    int gq = lane >> 2, iq = lane & 3;

    for (int nb = 0; nb < 8; nb++) {
        float acc[2][4][4];
#pragma unroll
        for (int mt = 0; mt < 2; mt++)
#pragma unroll
            for (int nt = 0; nt < 4; nt++)
#pragma unroll
                for (int q = 0; q < 4; q++) acc[mt][nt][q] = 0.0f;

        for (int kc = 0; kc < 4; kc++) {
            int t = nb * 4 + kc;
            if (t + 2 < 32) issue_b(smem0, (t + 2) % 3, t + 2, tid);
            if (t < 30)       asm volatile("cp.async.wait_group 2;" ::: "memory");
            else if (t == 30) asm volatile("cp.async.wait_group 1;" ::: "memory");
            else              asm volatile("cp.async.wait_group 0;" ::: "memory");
            __syncthreads();

            uint32_t bst = b_base + (t % 3) * BSTG;
            uint32_t ab = a_base + kc * 128;
#pragma unroll
            for (int kh = 0; kh < 2; kh++) {
                uint32_t bfr[4][4];
#pragma unroll
                for (int nt = 0; nt < 4; nt++)
                    LDSM4(bfr[nt], bst + nt * (8 * B_PITCH) + kh * 64);
#pragma unroll
                for (int ks = 0; ks < 2; ks++) {
                    uint32_t afr[2][4];
#pragma unroll
                    for (int mt = 0; mt < 2; mt++)
                        LDSM4(afr[mt], ab + mt * (16 * A_PITCH) + kh * 64 + ks * 32);
#pragma unroll
                    for (int mt = 0; mt < 2; mt++)
#pragma unroll
                        for (int nt = 0; nt < 4; nt++)
                            MMA16816(acc[mt][nt], afr[mt], bfr[nt][ks * 2], bfr[nt][ks * 2 + 1]);
                }
            }
            __syncthreads();
        }

        // ---- epilogue phase 1: per-row running min ----
#pragma unroll
        for (int mt = 0; mt < 2; mt++) {
#pragma unroll
            for (int h = 0; h < 2; h++) {
                int mrow = warp_m * 32 + mt * 16 + gq + h * 8;
                float xv = xs[mrow];
                float dmin = 3.4e38f;
#pragma unroll
                for (int nt = 0; nt < 4; nt++) {
                    int nbase = nb * 128 + warp_n * 32 + nt * 8 + 2 * iq;
                    float d0 = (xv + es[nbase])     - 2.0f * acc[mt][nt][h * 2 + 0];
                    float d1 = (xv + es[nbase + 1]) - 2.0f * acc[mt][nt][h * 2 + 1];
                    dmin = fminf(dmin, fminf(d0, d1));
                }
                atomicMin(&rowmin[mrow], __float_as_int(dmin));
            }
        }
        __syncthreads();
        // ---- epilogue phase 2: tight capture ----
#pragma unroll
        for (int mt = 0; mt < 2; mt++) {
#pragma unroll
            for (int h = 0; h < 2; h++) {
                int mrow = warp_m * 32 + mt * 16 + gq + h * 8;
                float xv = xs[mrow];
                float thr = __int_as_float(rowmin[mrow]) + TAU;
#pragma unroll
                for (int nt = 0; nt < 4; nt++) {
                    int nbase = nb * 128 + warp_n * 32 + nt * 8 + 2 * iq;
                    float d0 = (xv + es[nbase])     - 2.0f * acc[mt][nt][h * 2 + 0];
                    float d1 = (xv + es[nbase + 1]) - 2.0f * acc[mt][nt][h * 2 + 1];
                    if (d0 <= thr) {
                        int slot = atomicAdd(&ccnt[mrow], 1);
                        if (slot < MAXCAND) cand[mrow * MAXCAND + slot] = nbase;
                    }
                    if (d1 <= thr) {
                        int slot = atomicAdd(&ccnt[mrow], 1);
                        if (slot < MAXCAND) cand[mrow * MAXCAND + slot] = nbase + 1;
                    }
                }
            }
        }
    }
    __syncthreads();

    // exact fp32 rescore: warp w handles rows w*8..w*8+7
    for (int rr = 0; rr < 8; rr++) {
        int rl = wid * 8 + rr;
        int row = n0 + rl;
        int cnt = ccnt[rl];
        float xx = g_xx[row];
        const float4* xr4 = (const float4*)(g_XT + (size_t)row * 256 + lane * 8);
        float4 xa = xr4[0], xb4 = xr4[1];
        float best = 3.4e38f; int bidx = 0x7fffffff;
        bool overflow = (cnt > MAXCAND);
        int total = overflow ? KCODES : cnt;
        for (int c = 0; c < total; c++) {
            int k = overflow ? c : cand[rl * MAXCAND + c];
            const float4* cr = (const float4*)(cb + (size_t)k * 256 + lane * 8);
            float4 ca = cr[0], cbv = cr[1];
            float p = xa.x * ca.x;
            p = fmaf(xa.y, ca.y, p);
            p = fmaf(xa.z, ca.z, p);
            p = fmaf(xa.w, ca.w, p);
            p = fmaf(xb4.x, cbv.x, p);
            p = fmaf(xb4.y, cbv.y, p);
            p = fmaf(xb4.z, cbv.z, p);
            p = fmaf(xb4.w, cbv.w, p);
#pragma unroll
            for (int m = 16; m; m >>= 1) p += __shfl_xor_sync(0xffffffffu, p, m);
            float dd = (xx + es[k]) - 2.0f * p;
            if (dd < best || (dd == best && k < bidx)) { best = dd; bidx = k; }
        }
        if (lane == 0) g_idx[row] = bidx;
    }
}

// ===== outputs: quantized + SSE + indices + one-hot slice, one kernel ======
// block (b, ct, ht): rows ht*32..+32 of batch b, channel cols ct*32..+32.
// The same block writes one-hot columns [ct*128, ct*128+128) of its 32 rows
// (ct spans 0..7 -> full 1024-col coverage), filling quant's idle DRAM lanes.
__global__ void k_quant2(const float* __restrict__ x, const float* __restrict__ cb,
                         float* __restrict__ outq, float* __restrict__ enc,
                         float* __restrict__ outi, int en, int ee, int ei) {
    __shared__ float xs[32][33];
    __shared__ float qs[32][33];
    __shared__ int ids[32];
    int bid = blockIdx.x;
    int b = bid >> 8, ct = (bid >> 5) & 7, ht = bid & 31;
    int tx = threadIdx.x & 31, ty = threadIdx.x >> 5;
    if (threadIdx.x < 32) ids[threadIdx.x] = g_idx[(b << 10) + ht * 32 + threadIdx.x];
#pragma unroll
    for (int r = 0; r < 4; r++)
        xs[ty + r * 8][tx] = x[(((size_t)b * 256 + ct * 32 + ty + r * 8) << 10) + ht * 32 + tx];
    __syncthreads();
#pragma unroll
    for (int r = 0; r < 4; r++) {
        int nl = ty + r * 8;
        qs[tx][nl] = cb[(size_t)ids[nl] * 256 + ct * 32 + tx];
    }
    __syncthreads();
    float local = 0.0f;
#pragma unroll
    for (int r = 0; r < 4; r++) {
        int cl = ty + r * 8;
        float in = xs[cl][tx];
        float q = qs[cl][tx];
        float diff = q - in;
        if (en) outq[(((size_t)b * 256 + ct * 32 + cl) << 10) + ht * 32 + tx] = in + diff;
        local = fmaf(diff, diff, local);
    }
    // indices (ct==0 blocks only)
    if (ei && ct == 0 && threadIdx.x < 32)
        outi[(b << 10) + ht * 32 + threadIdx.x] = (float)ids[threadIdx.x];
    // one-hot slice: cols [ct*128, ct*128+128) of this block's 32 rows
    if (ee) {
        int colbase = ct * 128;
        int cl = threadIdx.x & 127;
        int j0 = threadIdx.x >> 7;      // 0 or 1
        int col = colbase + cl;
#pragma unroll
        for (int j = 0; j < 32; j += 2) {
            int jj = j + j0;
            float v = (col == ids[jj]) ? 1.0f : 0.0f;
            enc[(size_t)((b << 10) + ht * 32 + jj) * 1024 + col] = v;
        }
    }
    __shared__ float red[256];
    red[threadIdx.x] = local;
    __syncthreads();
    for (int sfr = 128; sfr; sfr >>= 1) {
        if (threadIdx.x < sfr) red[threadIdx.x] += red[threadIdx.x + sfr];
        __syncthreads();
    }
    if (threadIdx.x == 0) g_partial[bid] = red[0];
}

__global__ void k_loss(float* __restrict__ out_loss) {
    __shared__ float red[256];
    float s = 0.0f;
    int base = threadIdx.x * 32;
#pragma unroll
    for (int i = 0; i < 32; i++) s += g_partial[base + i];
    red[threadIdx.x] = s;
    __syncthreads();
    for (int t = 128; t; t >>= 1) {
        if (threadIdx.x < t) red[threadIdx.x] += red[threadIdx.x + t];
        __syncthreads();
    }
    if (threadIdx.x == 0) {
        float m = red[0] / 8388608.0f;
        out_loss[0] = m + 0.25f * m;
    }
}

// ===========================================================================
extern "C" void kernel_launch(void* const* d_in, const int* in_sizes, int n_in,
                              void* d_out, int out_size) {
    const float* x  = (const float*)d_in[0];
    const float* cb = (const float*)d_in[1];
    if (n_in >= 2 && in_sizes[0] == KCODES * DDIM && in_sizes[1] == (int)Q_ELEMS) {
        const float* t = x; x = cb; cb = t;
    }
    float* out = (float*)d_out;

    long long os = (long long)out_size;
    long long off_loss = -1, off_q = -1, off_e = -1, off_i = -1;
    if (os == 1 + Q_ELEMS + E_ELEMS + I_ELEMS) {
        off_loss = 0; off_q = 1; off_e = 1 + Q_ELEMS; off_i = 1 + Q_ELEMS + E_ELEMS;
    } else if (os == Q_ELEMS) {
        off_q = 0;
    } else if (os == 1) {
        off_loss = 0;
    } else if (os == 1 + Q_ELEMS) {
        off_loss = 0; off_q = 1;
    } else {
        if (os >= 1) off_loss = 0;
        if (os >= 1 + Q_ELEMS) off_q = 1;
        if (os >= 1 + Q_ELEMS + E_ELEMS) off_e = 1 + Q_ELEMS;
        if (os >= 1 + Q_ELEMS + E_ELEMS + I_ELEMS) off_i = 1 + Q_ELEMS + E_ELEMS;
    }

    cudaFuncSetAttribute(k_dist_mma, cudaFuncAttributeMaxDynamicSharedMemorySize, DIST_SMEM);

    k_prep_cb<<<128, 256>>>(cb);
    k_splitxx<<<1024, 256>>>(x);
    k_dist_mma<<<512, 256, DIST_SMEM>>>(cb);

    k_quant2<<<8192, 256>>>(x, cb,
                            (off_q >= 0) ? (out + off_q) : out,
                            (off_e >= 0) ? (out + off_e) : out,
                            (off_i >= 0) ? (out + off_i) : out,
                            (off_q >= 0) ? 1 : 0,
                            (off_e >= 0) ? 1 : 0,
                            (off_i >= 0) ? 1 : 0);
    if (off_loss >= 0) k_loss<<<1, 256>>>(out + off_loss);
}